// round 3
// baseline (speedup 1.0000x reference)
#include <cuda_runtime.h>

#define N_NODES 10000
#define IN_CH   256
#define H       16
#define NCLASS  10
#define E1      320000
#define E2      960000
#define TOPO_LEN (N_NODES * H)   // 160000
#define GWC     2500
#define BN_EPS  1e-5f

// ---------------- scratch (static device globals; no allocation) -------------
__device__ float d_h[N_NODES * H];        // relu(x@feat_W+b) == xs0
__device__ float d_topo[TOPO_LEN];        // [N,H] flat
__device__ float d_c1[N_NODES * 2 * H];   // after BN
__device__ float d_c2[N_NODES * 4 * H];
__device__ int   d_rp1[N_NODES + 1];
__device__ int   d_rp2[N_NODES + 1];

// ---------------- row pointers from sorted COO rows (binary search) ----------
__global__ void build_rowptr_kernel(const int* __restrict__ r1,
                                    const int* __restrict__ r2) {
    int t = blockIdx.x * blockDim.x + threadIdx.x;
    if (t <= N_NODES) {
        int lo = 0, hi = E1;
        while (lo < hi) { int m = (lo + hi) >> 1; if (r1[m] < t) lo = m + 1; else hi = m; }
        d_rp1[t] = lo;
    } else {
        int v = t - (N_NODES + 1);
        if (v <= N_NODES) {
            int lo = 0, hi = E2;
            while (lo < hi) { int m = (lo + hi) >> 1; if (r2[m] < v) lo = m + 1; else hi = m; }
            d_rp2[v] = lo;
        }
    }
}

// ---------------- h = relu(x @ feat_W + feat_b) ------------------------------
// block = (16 cols, 16 rows); feat_W staged in shared (16 KB).
__global__ void feat_kernel(const float* __restrict__ x,
                            const float* __restrict__ W,
                            const float* __restrict__ b) {
    __shared__ float Ws[IN_CH * H];
    int tid = threadIdx.y * 16 + threadIdx.x;
    for (int i = tid; i < IN_CH * H; i += 256) Ws[i] = W[i];
    __syncthreads();
    int row = blockIdx.x * 16 + threadIdx.y;
    int c   = threadIdx.x;
    const float* xr = x + row * IN_CH;
    float acc = b[c];
#pragma unroll 8
    for (int k = 0; k < IN_CH; k++) acc = fmaf(xr[k], Ws[k * H + c], acc);
    d_h[row * H + c] = fmaxf(acc, 0.0f);
}

// ---------------- topo = (gwc_flat @ gll_W + gll_b)  [the 1.6GB stream] ------
// one float4 output column-group per thread, unroll-10 over i for MLP.
__global__ void topo_kernel(const float* __restrict__ g,
                            const float* __restrict__ W,
                            const float* __restrict__ gb) {
    __shared__ float gs[GWC];
    for (int i = threadIdx.x; i < GWC; i += blockDim.x) gs[i] = g[i];
    __syncthreads();
    int j = blockIdx.x * blockDim.x + threadIdx.x;   // 0 .. 39999 (float4 units)
    if (j >= TOPO_LEN / 4) return;
    const float4* W4 = (const float4*)W;
    float4 acc = ((const float4*)gb)[j];
    const int stride = TOPO_LEN / 4;                 // 40000
#pragma unroll 1
    for (int i = 0; i < GWC; i += 10) {
        float4 w[10];
#pragma unroll
        for (int u = 0; u < 10; u++)
            w[u] = __ldcs(&W4[(long)(i + u) * stride + j]);
#pragma unroll
        for (int u = 0; u < 10; u++) {
            float gv = gs[i + u];
            acc.x = fmaf(gv, w[u].x, acc.x);
            acc.y = fmaf(gv, w[u].y, acc.y);
            acc.z = fmaf(gv, w[u].z, acc.z);
            acc.w = fmaf(gv, w[u].w, acc.w);
        }
    }
    ((float4*)d_topo)[j] = acc;
}

// ---------------- SpMM pass 1 (h -> c1) + fused BN ---------------------------
// one warp per row; lanes split into 2 edge-groups x 16 features.
__global__ void spmm1_kernel(const int* __restrict__ col1, const float* __restrict__ val1,
                             const int* __restrict__ col2, const float* __restrict__ val2,
                             const float* __restrict__ gamma, const float* __restrict__ beta,
                             const float* __restrict__ mean,  const float* __restrict__ var) {
    int warp = (blockIdx.x * blockDim.x + threadIdx.x) >> 5;
    if (warp >= N_NODES) return;
    int lane = threadIdx.x & 31;
    int f = lane & 15, gsel = lane >> 4;

    float acc1 = 0.0f;
    {
        int e0 = d_rp1[warp], e1 = d_rp1[warp + 1];
        for (int e = e0 + gsel; e < e1; e += 2) {
            int c = __ldg(&col1[e]); float v = __ldg(&val1[e]);
            acc1 = fmaf(v, d_h[c * H + f], acc1);
        }
    }
    acc1 += __shfl_xor_sync(0xffffffffu, acc1, 16);

    float acc2 = 0.0f;
    {
        int e0 = d_rp2[warp], e1 = d_rp2[warp + 1];
        for (int e = e0 + gsel; e < e1; e += 2) {
            int c = __ldg(&col2[e]); float v = __ldg(&val2[e]);
            acc2 = fmaf(v, d_h[c * H + f], acc2);
        }
    }
    acc2 += __shfl_xor_sync(0xffffffffu, acc2, 16);

    if (lane < 16) {
        float sc1 = gamma[f] * rsqrtf(var[f] + BN_EPS);
        d_c1[warp * 32 + f] = (acc1 - mean[f]) * sc1 + beta[f];
        float sc2 = gamma[16 + f] * rsqrtf(var[16 + f] + BN_EPS);
        d_c1[warp * 32 + 16 + f] = (acc2 - mean[16 + f]) * sc2 + beta[16 + f];
    }
}

// ---------------- SpMM pass 2 (c1 -> c2) -------------------------------------
// one warp per row; 32 lanes = 32 features, serial over edges (col/val broadcast).
__global__ void spmm2_kernel(const int* __restrict__ col1, const float* __restrict__ val1,
                             const int* __restrict__ col2, const float* __restrict__ val2) {
    int warp = (blockIdx.x * blockDim.x + threadIdx.x) >> 5;
    if (warp >= N_NODES) return;
    int lane = threadIdx.x & 31;

    float a = 0.0f;
    {
        int e0 = d_rp1[warp], e1 = d_rp1[warp + 1];
        for (int e = e0; e < e1; e++) {
            int c = __ldg(&col1[e]); float v = __ldg(&val1[e]);
            a = fmaf(v, d_c1[c * 32 + lane], a);
        }
    }
    float b = 0.0f;
    {
        int e0 = d_rp2[warp], e1 = d_rp2[warp + 1];
        for (int e = e0; e < e1; e++) {
            int c = __ldg(&col2[e]); float v = __ldg(&val2[e]);
            b = fmaf(v, d_c1[c * 32 + lane], b);
        }
    }
    d_c2[warp * 64 + lane]      = a;
    d_c2[warp * 64 + 32 + lane] = b;
}

// ---------------- final: [xs0|c1|c2|topo] @ fin_W + b -> log_softmax ---------
__global__ void final_kernel(const float* __restrict__ fW,
                             const float* __restrict__ fb,
                             float* __restrict__ out) {
    __shared__ float Wf[128 * NCLASS];
    __shared__ float bs[NCLASS];
    int tid = threadIdx.x;
    for (int i = tid; i < 128 * NCLASS; i += blockDim.x) Wf[i] = fW[i];
    if (tid < NCLASS) bs[tid] = fb[tid];
    __syncthreads();
    int r = blockIdx.x * blockDim.x + tid;
    if (r >= N_NODES) return;

    float o[NCLASS];
#pragma unroll
    for (int c = 0; c < NCLASS; c++) o[c] = bs[c];

    const float* xs = d_h + r * 16;
#pragma unroll
    for (int f = 0; f < 16; f++) {
        float v = xs[f];
#pragma unroll
        for (int c = 0; c < NCLASS; c++) o[c] = fmaf(v, Wf[f * NCLASS + c], o[c]);
    }
    const float* c1r = d_c1 + r * 32;
#pragma unroll
    for (int f = 0; f < 32; f++) {
        float v = c1r[f];
#pragma unroll
        for (int c = 0; c < NCLASS; c++) o[c] = fmaf(v, Wf[(16 + f) * NCLASS + c], o[c]);
    }
    const float* c2r = d_c2 + r * 64;
#pragma unroll
    for (int f = 0; f < 64; f++) {
        float v = c2r[f];
#pragma unroll
        for (int c = 0; c < NCLASS; c++) o[c] = fmaf(v, Wf[(48 + f) * NCLASS + c], o[c]);
    }
    const float* tr = d_topo + r * 16;
#pragma unroll
    for (int f = 0; f < 16; f++) {
        float v = tr[f];
#pragma unroll
        for (int c = 0; c < NCLASS; c++) o[c] = fmaf(v, Wf[(112 + f) * NCLASS + c], o[c]);
    }

    float m = o[0];
#pragma unroll
    for (int c = 1; c < NCLASS; c++) m = fmaxf(m, o[c]);
    float s = 0.0f;
#pragma unroll
    for (int c = 0; c < NCLASS; c++) s += expf(o[c] - m);
    float ls = logf(s);
#pragma unroll
    for (int c = 0; c < NCLASS; c++) out[r * NCLASS + c] = o[c] - m - ls;
}

// ---------------- launch -----------------------------------------------------
extern "C" void kernel_launch(void* const* d_in, const int* in_sizes, int n_in,
                              void* d_out, int out_size) {
    const float* x        = (const float*)d_in[0];
    const float* gwc      = (const float*)d_in[1];
    const int*   a1_row   = (const int*)  d_in[2];
    const int*   a1_col   = (const int*)  d_in[3];
    const float* a1_val   = (const float*)d_in[4];
    const int*   a2_row   = (const int*)  d_in[5];
    const int*   a2_col   = (const int*)  d_in[6];
    const float* a2_val   = (const float*)d_in[7];
    const float* feat_W   = (const float*)d_in[8];
    const float* feat_b   = (const float*)d_in[9];
    const float* gll_W    = (const float*)d_in[10];
    const float* gll_b    = (const float*)d_in[11];
    const float* bn_gamma = (const float*)d_in[12];
    const float* bn_beta  = (const float*)d_in[13];
    const float* bn_mean  = (const float*)d_in[14];
    const float* bn_var   = (const float*)d_in[15];
    const float* fin_W    = (const float*)d_in[16];
    const float* fin_b    = (const float*)d_in[17];
    float* out = (float*)d_out;

    build_rowptr_kernel<<<(2 * (N_NODES + 1) + 255) / 256, 256>>>(a1_row, a2_row);
    feat_kernel<<<N_NODES / 16, dim3(16, 16)>>>(x, feat_W, feat_b);
    spmm1_kernel<<<(N_NODES * 32 + 255) / 256, 256>>>(a1_col, a1_val, a2_col, a2_val,
                                                      bn_gamma, bn_beta, bn_mean, bn_var);
    spmm2_kernel<<<(N_NODES * 32 + 255) / 256, 256>>>(a1_col, a1_val, a2_col, a2_val);
    topo_kernel<<<(TOPO_LEN / 4 + 127) / 128, 128>>>(gwc, gll_W, gll_b);
    final_kernel<<<(N_NODES + 127) / 128, 128>>>(fin_W, fin_b, out);
}

// round 4
// speedup vs baseline: 1.5294x; 1.5294x over previous
#include <cuda_runtime.h>

#define N_NODES 10000
#define IN_CH   256
#define H       16
#define NCLASS  10
#define E1      320000
#define E2      960000
#define TOPO_LEN (N_NODES * H)   // 160000
#define GWC     2500
#define BN_EPS  1e-5f

#define TSPLIT   4
#define GWC_PART (GWC / TSPLIT)      // 625
#define J4       (TOPO_LEN / 4)      // 40000 float4 outputs
#define JBLK     256
#define JGRID    ((J4 + JBLK - 1) / JBLK)   // 157

// ---------------- scratch (static device globals; no allocation) -------------
__device__ float d_h[N_NODES * H];            // relu(x@feat_W+b) == xs0
__device__ float d_topo_part[TSPLIT * TOPO_LEN];
__device__ float d_c1[N_NODES * 2 * H];       // after BN
__device__ float d_c2[N_NODES * 4 * H];
__device__ int   d_rp1[N_NODES + 1];
__device__ int   d_rp2[N_NODES + 1];

// ---------------- row pointers from sorted COO rows (binary search) ----------
__global__ void build_rowptr_kernel(const int* __restrict__ r1,
                                    const int* __restrict__ r2) {
    int t = blockIdx.x * blockDim.x + threadIdx.x;
    if (t <= N_NODES) {
        int lo = 0, hi = E1;
        while (lo < hi) { int m = (lo + hi) >> 1; if (r1[m] < t) lo = m + 1; else hi = m; }
        d_rp1[t] = lo;
    } else {
        int v = t - (N_NODES + 1);
        if (v <= N_NODES) {
            int lo = 0, hi = E2;
            while (lo < hi) { int m = (lo + hi) >> 1; if (r2[m] < v) lo = m + 1; else hi = m; }
            d_rp2[v] = lo;
        }
    }
}

// ---------------- h = relu(x @ feat_W + feat_b) ------------------------------
__global__ void feat_kernel(const float* __restrict__ x,
                            const float* __restrict__ W,
                            const float* __restrict__ b) {
    __shared__ float Ws[IN_CH * H];
    int tid = threadIdx.y * 16 + threadIdx.x;
    for (int i = tid; i < IN_CH * H; i += 256) Ws[i] = W[i];
    __syncthreads();
    int row = blockIdx.x * 16 + threadIdx.y;
    int c   = threadIdx.x;
    const float* xr = x + row * IN_CH;
    float acc = b[c];
#pragma unroll 8
    for (int k = 0; k < IN_CH; k++) acc = fmaf(xr[k], Ws[k * H + c], acc);
    d_h[row * H + c] = fmaxf(acc, 0.0f);
}

// ---------------- topo partials: i-split GEMV over the 1.6GB matrix ----------
// blockIdx.y = i-partition (625 rows each). Single full-chip wave:
// 628 blocks x 256 thr, ~40 regs -> >=5 blocks/SM resident.
__global__ void __launch_bounds__(JBLK)
topo_kernel(const float* __restrict__ g,
            const float* __restrict__ W,
            const float* __restrict__ gb) {
    __shared__ float gs[GWC_PART];
    const int part = blockIdx.y;
    const int ibase = part * GWC_PART;
    for (int i = threadIdx.x; i < GWC_PART; i += JBLK) gs[i] = g[ibase + i];
    __syncthreads();
    int j = blockIdx.x * JBLK + threadIdx.x;
    if (j >= J4) return;
    const float4* W4 = (const float4*)W;
    float4 acc;
    if (part == 0) acc = ((const float4*)gb)[j];
    else           acc = make_float4(0.f, 0.f, 0.f, 0.f);
    const long stride = J4;
    const float4* Wp = W4 + (long)ibase * stride + j;
#pragma unroll 1
    for (int i = 0; i < GWC_PART; i += 5) {
        float4 w[5];
#pragma unroll
        for (int u = 0; u < 5; u++)
            w[u] = __ldcs(Wp + (long)(i + u) * stride);
#pragma unroll
        for (int u = 0; u < 5; u++) {
            float gv = gs[i + u];
            acc.x = fmaf(gv, w[u].x, acc.x);
            acc.y = fmaf(gv, w[u].y, acc.y);
            acc.z = fmaf(gv, w[u].z, acc.z);
            acc.w = fmaf(gv, w[u].w, acc.w);
        }
    }
    ((float4*)d_topo_part)[part * J4 + j] = acc;
}

// ---------------- SpMM pass 1 (h -> c1) + fused BN ---------------------------
__global__ void spmm1_kernel(const int* __restrict__ col1, const float* __restrict__ val1,
                             const int* __restrict__ col2, const float* __restrict__ val2,
                             const float* __restrict__ gamma, const float* __restrict__ beta,
                             const float* __restrict__ mean,  const float* __restrict__ var) {
    int warp = (blockIdx.x * blockDim.x + threadIdx.x) >> 5;
    if (warp >= N_NODES) return;
    int lane = threadIdx.x & 31;
    int f = lane & 15, gsel = lane >> 4;

    float acc1 = 0.0f;
    {
        int e0 = d_rp1[warp], e1 = d_rp1[warp + 1];
        for (int e = e0 + gsel; e < e1; e += 2) {
            int c = __ldg(&col1[e]); float v = __ldg(&val1[e]);
            acc1 = fmaf(v, d_h[c * H + f], acc1);
        }
    }
    acc1 += __shfl_xor_sync(0xffffffffu, acc1, 16);

    float acc2 = 0.0f;
    {
        int e0 = d_rp2[warp], e1 = d_rp2[warp + 1];
        for (int e = e0 + gsel; e < e1; e += 2) {
            int c = __ldg(&col2[e]); float v = __ldg(&val2[e]);
            acc2 = fmaf(v, d_h[c * H + f], acc2);
        }
    }
    acc2 += __shfl_xor_sync(0xffffffffu, acc2, 16);

    if (lane < 16) {
        float sc1 = gamma[f] * rsqrtf(var[f] + BN_EPS);
        d_c1[warp * 32 + f] = (acc1 - mean[f]) * sc1 + beta[f];
        float sc2 = gamma[16 + f] * rsqrtf(var[16 + f] + BN_EPS);
        d_c1[warp * 32 + 16 + f] = (acc2 - mean[16 + f]) * sc2 + beta[16 + f];
    }
}

// ---------------- SpMM pass 2 (c1 -> c2) -------------------------------------
__global__ void spmm2_kernel(const int* __restrict__ col1, const float* __restrict__ val1,
                             const int* __restrict__ col2, const float* __restrict__ val2) {
    int warp = (blockIdx.x * blockDim.x + threadIdx.x) >> 5;
    if (warp >= N_NODES) return;
    int lane = threadIdx.x & 31;

    float a = 0.0f;
    {
        int e0 = d_rp1[warp], e1 = d_rp1[warp + 1];
        for (int e = e0; e < e1; e++) {
            int c = __ldg(&col1[e]); float v = __ldg(&val1[e]);
            a = fmaf(v, d_c1[c * 32 + lane], a);
        }
    }
    float b = 0.0f;
    {
        int e0 = d_rp2[warp], e1 = d_rp2[warp + 1];
        for (int e = e0; e < e1; e++) {
            int c = __ldg(&col2[e]); float v = __ldg(&val2[e]);
            b = fmaf(v, d_c1[c * 32 + lane], b);
        }
    }
    d_c2[warp * 64 + lane]      = a;
    d_c2[warp * 64 + 32 + lane] = b;
}

// ---------------- final: [xs0|c1|c2|topo] @ fin_W + b -> log_softmax ---------
__global__ void final_kernel(const float* __restrict__ fW,
                             const float* __restrict__ fb,
                             float* __restrict__ out) {
    __shared__ float Wf[128 * NCLASS];
    __shared__ float bs[NCLASS];
    int tid = threadIdx.x;
    for (int i = tid; i < 128 * NCLASS; i += blockDim.x) Wf[i] = fW[i];
    if (tid < NCLASS) bs[tid] = fb[tid];
    __syncthreads();
    int r = blockIdx.x * blockDim.x + tid;
    if (r >= N_NODES) return;

    float o[NCLASS];
#pragma unroll
    for (int c = 0; c < NCLASS; c++) o[c] = bs[c];

    const float* xs = d_h + r * 16;
#pragma unroll
    for (int f = 0; f < 16; f++) {
        float v = xs[f];
#pragma unroll
        for (int c = 0; c < NCLASS; c++) o[c] = fmaf(v, Wf[f * NCLASS + c], o[c]);
    }
    const float* c1r = d_c1 + r * 32;
#pragma unroll
    for (int f = 0; f < 32; f++) {
        float v = c1r[f];
#pragma unroll
        for (int c = 0; c < NCLASS; c++) o[c] = fmaf(v, Wf[(16 + f) * NCLASS + c], o[c]);
    }
    const float* c2r = d_c2 + r * 64;
#pragma unroll
    for (int f = 0; f < 64; f++) {
        float v = c2r[f];
#pragma unroll
        for (int c = 0; c < NCLASS; c++) o[c] = fmaf(v, Wf[(48 + f) * NCLASS + c], o[c]);
    }
    // topo = sum of TSPLIT partials (bias folded into partial 0)
#pragma unroll
    for (int f = 0; f < 16; f++) {
        float v = d_topo_part[0 * TOPO_LEN + r * 16 + f];
#pragma unroll
        for (int p = 1; p < TSPLIT; p++)
            v += d_topo_part[p * TOPO_LEN + r * 16 + f];
#pragma unroll
        for (int c = 0; c < NCLASS; c++) o[c] = fmaf(v, Wf[(112 + f) * NCLASS + c], o[c]);
    }

    float m = o[0];
#pragma unroll
    for (int c = 1; c < NCLASS; c++) m = fmaxf(m, o[c]);
    float s = 0.0f;
#pragma unroll
    for (int c = 0; c < NCLASS; c++) s += expf(o[c] - m);
    float ls = logf(s);
#pragma unroll
    for (int c = 0; c < NCLASS; c++) out[r * NCLASS + c] = o[c] - m - ls;
}

// ---------------- launch (fork-join: topo overlaps the spmm chain) -----------
extern "C" void kernel_launch(void* const* d_in, const int* in_sizes, int n_in,
                              void* d_out, int out_size) {
    const float* x        = (const float*)d_in[0];
    const float* gwc      = (const float*)d_in[1];
    const int*   a1_row   = (const int*)  d_in[2];
    const int*   a1_col   = (const int*)  d_in[3];
    const float* a1_val   = (const float*)d_in[4];
    const int*   a2_row   = (const int*)  d_in[5];
    const int*   a2_col   = (const int*)  d_in[6];
    const float* a2_val   = (const float*)d_in[7];
    const float* feat_W   = (const float*)d_in[8];
    const float* feat_b   = (const float*)d_in[9];
    const float* gll_W    = (const float*)d_in[10];
    const float* gll_b    = (const float*)d_in[11];
    const float* bn_gamma = (const float*)d_in[12];
    const float* bn_beta  = (const float*)d_in[13];
    const float* bn_mean  = (const float*)d_in[14];
    const float* bn_var   = (const float*)d_in[15];
    const float* fin_W    = (const float*)d_in[16];
    const float* fin_b    = (const float*)d_in[17];
    float* out = (float*)d_out;

    static cudaStream_t s2 = nullptr;
    static cudaEvent_t  eFork = nullptr, eJoin = nullptr;
    if (s2 == nullptr) {
        cudaStreamCreateWithFlags(&s2, cudaStreamNonBlocking);
        cudaEventCreateWithFlags(&eFork, cudaEventDisableTiming);
        cudaEventCreateWithFlags(&eJoin, cudaEventDisableTiming);
    }

    // fork: topo GEMV (DRAM-bound) on s2, spmm chain (L2-bound) on main stream
    cudaEventRecord(eFork, 0);
    cudaStreamWaitEvent(s2, eFork, 0);
    topo_kernel<<<dim3(JGRID, TSPLIT), JBLK, 0, s2>>>(gwc, gll_W, gll_b);

    build_rowptr_kernel<<<(2 * (N_NODES + 1) + 255) / 256, 256>>>(a1_row, a2_row);
    feat_kernel<<<N_NODES / 16, dim3(16, 16)>>>(x, feat_W, feat_b);
    spmm1_kernel<<<(N_NODES * 32 + 255) / 256, 256>>>(a1_col, a1_val, a2_col, a2_val,
                                                      bn_gamma, bn_beta, bn_mean, bn_var);
    spmm2_kernel<<<(N_NODES * 32 + 255) / 256, 256>>>(a1_col, a1_val, a2_col, a2_val);

    // join: final needs both branches
    cudaEventRecord(eJoin, s2);
    cudaStreamWaitEvent(0, eJoin, 0);
    final_kernel<<<(N_NODES + 127) / 128, 128>>>(fin_W, fin_b, out);
}